// round 7
// baseline (speedup 1.0000x reference)
#include <cuda_runtime.h>
#include <cstdint>

#define BDIM 288
#define DISP 4
#define ND 9
#define CH 128
#define HH 96
#define WW 160
#define NB 8
#define TY 8
#define TX 32
#define CCH 4
#define NBUF 3
#define NSTAGE (CH / CCH)        // 32
#define FRS 36
#define FCS (TY * FRS)           // 288 floats / channel
#define SRS 44
#define SROWS (TY + 2 * DISP)    // 16
#define SCS (SROWS * SRS)        // 704 floats / channel
#define CHB (HH * WW * 4)        // bytes per channel plane

typedef unsigned long long u64;
typedef unsigned int u32;

struct F2 { float lo, hi; };

static __device__ __forceinline__ u64 pk(float lo, float hi) {
    u64 r; asm("mov.b64 %0, {%1, %2};" : "=l"(r) : "f"(lo), "f"(hi)); return r;
}
static __device__ __forceinline__ F2 unp(u64 v) {
    F2 r; asm("mov.b64 {%0, %1}, %2;" : "=f"(r.lo), "=f"(r.hi) : "l"(v)); return r;
}
static __device__ __forceinline__ void fma2(u64 &d, u64 a, u64 b) {
    asm("fma.rn.f32x2 %0, %1, %2, %0;" : "+l"(d) : "l"(a), "l"(b));
}
static __device__ __forceinline__ void cpa16(u32 saddr, const void* gptr, int srcsz) {
    asm volatile("cp.async.cg.shared.global [%0], [%1], 16, %2;"
                 :: "r"(saddr), "l"(gptr), "r"(srcsz));
}
static __device__ __forceinline__ void cpa_commit() {
    asm volatile("cp.async.commit_group;");
}
template <int N> static __device__ __forceinline__ void cpa_wait() {
    asm volatile("cp.async.wait_group %0;" :: "n"(N));
}

__global__ __launch_bounds__(BDIM, 2)
void corr_kernel(const float* __restrict__ first,
                 const float* __restrict__ second,
                 float* __restrict__ out) {
    __shared__ __align__(16) float sF[NBUF][CCH * FCS];   // 13824 B
    __shared__ __align__(16) float sS[NBUF][CCH * SCS];   // 33792 B

    const int tid = threadIdx.x;
    const int b   = blockIdx.z;
    const int y0  = blockIdx.y * TY;
    const int x0  = blockIdx.x * TX;

    const int d    = tid >> 5;
    const int lane = tid & 31;
    const int ty   = lane >> 2;
    const int xg   = lane & 3;

    const u32 sF0 = (u32)__cvta_generic_to_shared(&sF[0][0]);
    const u32 sS0 = (u32)__cvta_generic_to_shared(&sS[0][0]);

    // ---- persistent staging assignments (32-bit byte offsets) ----
    u32 g2off = 0, soff2 = 0; int ok2 = 0;          // threads < 160: second tile
    u32 g1off0 = 0, g1off1 = 0, soff1_0 = 0, soff1_1 = 0;  // threads >= 160: first

    if (tid < 160) {
        const int r2 = tid / 10;
        const int q2 = tid - r2 * 10;
        const int gy = y0 - DISP + r2;
        const int gx = x0 - DISP + 4 * q2;
        ok2 = (((unsigned)gy < HH) && ((unsigned)gx <= (WW - 4))) ? 16 : 0;
        const int cgy = ok2 ? gy : 0;
        const int cgx = ok2 ? gx : 0;
        g2off = (u32)(((b * CH * HH + cgy) * WW + cgx) * 4);
        soff2 = (u32)((r2 * SRS + 4 * q2) * 4);
    } else {
        const int i = tid - 160;
        #pragma unroll
        for (int k = 0; k < 2; k++) {
            const int qid = 2 * i + k;
            const int ca  = qid >> 6;
            const int p   = qid & 63;
            const int ra  = p >> 3;
            const int xqa = p & 7;
            const u32 go = (u32)((((b * CH + ca) * HH + y0 + ra) * WW + x0 + 4 * xqa) * 4);
            const u32 so = (u32)((ca * FCS + ra * FRS + 4 * xqa) * 4);
            if (k == 0) { g1off0 = go; soff1_0 = so; } else { g1off1 = go; soff1_1 = so; }
        }
    }

    const char* firstB  = (const char*)first;
    const char* secondB = (const char*)second;

    u64 acc[36];
    #pragma unroll
    for (int i = 0; i < 36; i++) acc[i] = 0ull;

    // stage s into buffer bi (bi compile-time at every call site)
    auto stage = [&](int s, int bi) {
        const u32 coff = (u32)(s * CCH) * (u32)CHB;
        if (tid < 160) {
            const u32 sSb = sS0 + (u32)(bi * CCH * SCS * 4) + soff2;
            #pragma unroll
            for (int c = 0; c < CCH; c++)
                cpa16(sSb + (u32)(c * SCS * 4), secondB + g2off + coff + c * CHB, ok2);
        } else {
            const u32 sFb = sF0 + (u32)(bi * CCH * FCS * 4);
            cpa16(sFb + soff1_0, firstB + g1off0 + coff, 16);
            cpa16(sFb + soff1_1, firstB + g1off1 + coff, 16);
        }
    };

    auto compute = [&](int br) {   // br compile-time
        const float* fptr = &sF[br][ty * FRS + 8 * xg];
        const float* sptr = &sS[br][(ty + d) * SRS + 8 * xg];
        #pragma unroll
        for (int cc = 0; cc < CCH; cc++) {
            const ulonglong2 F01 = *reinterpret_cast<const ulonglong2*>(fptr + cc * FCS);
            const ulonglong2 F23 = *reinterpret_cast<const ulonglong2*>(fptr + cc * FCS + 4);
            const ulonglong2 E01 = *reinterpret_cast<const ulonglong2*>(sptr + cc * SCS);
            const ulonglong2 E23 = *reinterpret_cast<const ulonglong2*>(sptr + cc * SCS + 4);
            const ulonglong2 E45 = *reinterpret_cast<const ulonglong2*>(sptr + cc * SCS + 8);
            const ulonglong2 E67 = *reinterpret_cast<const ulonglong2*>(sptr + cc * SCS + 12);

            const F2 a0 = unp(E01.x), a1 = unp(E01.y);
            const F2 a2 = unp(E23.x), a3 = unp(E23.y);
            const F2 a4 = unp(E45.x), a5 = unp(E45.y);
            const F2 a6 = unp(E67.x), a7 = unp(E67.y);

            u64 P[15];
            P[0]  = E01.x;            P[2]  = E01.y;
            P[4]  = E23.x;            P[6]  = E23.y;
            P[8]  = E45.x;            P[10] = E45.y;
            P[12] = E67.x;            P[14] = E67.y;
            P[1]  = pk(a0.hi, a1.lo); P[3]  = pk(a1.hi, a2.lo);
            P[5]  = pk(a2.hi, a3.lo); P[7]  = pk(a3.hi, a4.lo);
            P[9]  = pk(a4.hi, a5.lo); P[11] = pk(a5.hi, a6.lo);
            P[13] = pk(a6.hi, a7.lo);

            #pragma unroll
            for (int j = 0; j < ND; j++) {
                fma2(acc[j],      F01.x, P[j]);
                fma2(acc[9 + j],  F01.y, P[2 + j]);
                fma2(acc[18 + j], F23.x, P[4 + j]);
                fma2(acc[27 + j], F23.y, P[6 + j]);
            }
        }
    };

    // mode 0: wait<1>, stage(s+2, bw); mode 1: wait<1>; mode 2: wait<0>
    auto iter = [&](int s, int br, int bw, int mode) {
        if (mode == 0) {
            cpa_wait<1>();
            __syncthreads();
            stage(s + 2, bw);
            cpa_commit();
        } else if (mode == 1) {
            cpa_wait<1>();
            __syncthreads();
        } else {
            cpa_wait<0>();
            __syncthreads();
        }
        compute(br);
        __syncthreads();
    };

    stage(0, 0); cpa_commit();
    stage(1, 1); cpa_commit();

    #pragma unroll 1
    for (int t = 0; t < 10; t++) {
        const int s = 3 * t;
        iter(s + 0, 0, 2, 0);
        iter(s + 1, 1, 0, 0);
        iter(s + 2, 2, 1, 0);
    }
    iter(30, 0, 2, 1);
    iter(31, 1, 0, 2);

    // ---- epilogue: chan = dy*9 + dx (dx fastest) ----
    const float inv_c = 1.0f / (float)CH;
    const int gy = y0 + ty;
    const int gx = x0 + 8 * xg;
    char* outB = (char*)out;
    u32 obase = (u32)((((b * 81 + d * ND) * HH + gy) * WW + gx) * 4);
    #pragma unroll
    for (int j = 0; j < ND; j++) {
        float* o = (float*)(outB + obase);
        obase += (u32)(HH * WW * 4);
        const F2 r0 = unp(acc[j]);
        const F2 r1 = unp(acc[9 + j]);
        const F2 r2 = unp(acc[18 + j]);
        const F2 r3 = unp(acc[27 + j]);
        float4 v0 = make_float4(r0.lo * inv_c, r0.hi * inv_c, r1.lo * inv_c, r1.hi * inv_c);
        float4 v1 = make_float4(r2.lo * inv_c, r2.hi * inv_c, r3.lo * inv_c, r3.hi * inv_c);
        *reinterpret_cast<float4*>(o)     = v0;
        *reinterpret_cast<float4*>(o + 4) = v1;
    }
}

extern "C" void kernel_launch(void* const* d_in, const int* in_sizes, int n_in,
                              void* d_out, int out_size) {
    const float* first  = (const float*)d_in[0];
    const float* second = (const float*)d_in[1];
    float* out = (float*)d_out;
    (void)in_sizes; (void)n_in; (void)out_size;

    dim3 grid(WW / TX, HH / TY, NB);   // (5, 12, 8)
    corr_kernel<<<grid, BDIM>>>(first, second, out);
}